// round 5
// baseline (speedup 1.0000x reference)
#include <cuda_runtime.h>
#include <cuda_bf16.h>

#define BT   32
#define NPTS 128
#define DIM  64
#define AH   256   // ATTN_HID
#define PH   64    // POS_HID
#define PIN  34
#define JT   64    // j-tile

typedef unsigned long long u64;

// ---------------- f32x2 packed helpers ----------------
__device__ __forceinline__ u64 pk2(float x) {
    u64 r; asm("mov.b64 %0,{%1,%1};" : "=l"(r) : "f"(x)); return r;
}
__device__ __forceinline__ u64 pk(float lo, float hi) {
    u64 r; asm("mov.b64 %0,{%1,%2};" : "=l"(r) : "f"(lo), "f"(hi)); return r;
}
__device__ __forceinline__ void fm2(u64& d, u64 a, u64 b) {
    asm("fma.rn.f32x2 %0,%1,%2,%0;" : "+l"(d) : "l"(a), "l"(b));
}
__device__ __forceinline__ float2 up2(u64 v) {
    float2 f; asm("mov.b64 {%0,%1},%2;" : "=f"(f.x), "=f"(f.y) : "l"(v)); return f;
}

// ---------------- device scratch ----------------
__device__ float g_A [BT*NPTS*DIM];   // p @ pm_w1.T
__device__ float g_U [BT*NPTS*AH];    // q @ am_w1.T
__device__ float g_WK[BT*NPTS*AH];    // k @ am_w1.T
__device__ float g_V [BT*NPTS*DIM];   // v
__device__ float g_WcT  [PH*AH];      // [h][m]
__device__ float g_AMW2T[AH*DIM];     // [m][d]
__device__ float g_PW2T [PH*DIM];     // [h][d]
__device__ float g_cc   [AH];         // am_b1 + pm_b2 @ am_w1.T

// ---------------- kernel 0: weight-derived tensors (parallel, 70 blocks) ----
__global__ void prep_weights(const float* __restrict__ pm_w2,
                             const float* __restrict__ am_w1,
                             const float* __restrict__ am_b1,
                             const float* __restrict__ pm_b2,
                             const float* __restrict__ am_w2) {
    int b = blockIdx.x, t = threadIdx.x;
    if (b < 64) {                       // WcT[h][m] = dot(am_w1[m], pm_w2[:,h])
        int gid = b * 256 + t;          // 16384 outputs
        int m = gid >> 6, h = gid & 63; // lanes share m (broadcast), h coalesced-ish
        float s = 0.f;
#pragma unroll 8
        for (int d = 0; d < DIM; d++) s += am_w1[m*DIM + d] * pm_w2[d*PH + h];
        g_WcT[h*AH + m] = s;
    } else if (b < 68) {                // AMW2T transpose
        for (int i = (b-64)*256 + t; i < AH*DIM; i += 4*256) {
            int m = i >> 6, d = i & 63;
            g_AMW2T[m*DIM + d] = am_w2[d*AH + m];
        }
    } else if (b == 68) {               // PW2T transpose
        for (int i = t; i < PH*DIM; i += 256) {
            int h = i >> 6, d = i & 63;
            g_PW2T[h*DIM + d] = pm_w2[d*PH + h];
        }
    } else {                            // cc
        int m = t;
        float s = am_b1[m];
#pragma unroll 8
        for (int d = 0; d < DIM; d++) s += pm_b2[d] * am_w1[m*DIM + d];
        g_cc[m] = s;
    }
}

// ---------------- kernel 1: per-point precompute ----------------
__global__ void prep_points(const float* __restrict__ x,
                            const float* __restrict__ pos,
                            const float* __restrict__ w_qkv,
                            const float* __restrict__ pm_w1,
                            const float* __restrict__ am_w1) {
    __shared__ float sx[DIM], sp[PIN], sq[DIM], sk[DIM];
    int pt = blockIdx.x;            // bt*128 + n
    int bt = pt >> 7, n = pt & 127;
    int t  = threadIdx.x;           // 128 threads

    if (t < DIM) sx[t] = x[(size_t)pt*DIM + t];
    if (t < PIN) {
        int c = t / 17, j = t % 17;
        sp[t] = pos[(((size_t)bt*17 + j)*3 + c)*NPTS + n];
    }
    __syncthreads();

    for (int m = t; m < 3*DIM; m += 128) {
        const float4* wr = (const float4*)(w_qkv + m*DIM);
        float s = 0.f;
#pragma unroll
        for (int i = 0; i < DIM/4; i++) {
            float4 w  = wr[i];
            float4 xv = ((const float4*)sx)[i];
            s += w.x*xv.x + w.y*xv.y + w.z*xv.z + w.w*xv.w;
        }
        if      (m <   DIM) sq[m]        = s;
        else if (m < 2*DIM) sk[m-DIM]    = s;
        else g_V[(size_t)pt*DIM + (m-2*DIM)] = s;
    }
    if (t < DIM) {
        const float* wr = pm_w1 + t*PIN;
        float s = 0.f;
#pragma unroll
        for (int f = 0; f < PIN; f++) s += sp[f]*wr[f];
        g_A[(size_t)pt*DIM + t] = s;
    }
    __syncthreads();
    for (int m = t; m < AH; m += 128) {
        const float4* wr = (const float4*)(am_w1 + m*DIM);
        float su = 0.f, sw = 0.f;
#pragma unroll
        for (int i = 0; i < DIM/4; i++) {
            float4 w  = wr[i];
            float4 qv = ((const float4*)sq)[i];
            float4 kv = ((const float4*)sk)[i];
            su += w.x*qv.x + w.y*qv.y + w.z*qv.z + w.w*qv.w;
            sw += w.x*kv.x + w.y*kv.y + w.z*kv.z + w.w*kv.w;
        }
        g_U [(size_t)pt*AH + m] = su;
        g_WK[(size_t)pt*AH + m] = sw;
    }
}

// ---------------- kernel 2: fused pairwise MLPs + softmax + aggregate ------
// Block = one (bt, i). 512 threads (16 warps). j in 2 tiles of 64.
// smem float offsets (all 16-float aligned)
#define OFF_H1TD 0            // 64 k * 136 (j duplicated {v,v} + pad) = 8704
#define OFF_H1   8704         // 64 j * 68 row-major                  = 4352
#define OFF_H2   13056        // 64 j * 260 (256 m + pad)             = 16640
#define OFF_SIM  29696        // 128 j * 64 d                         = 8192
#define OFF_VP   37888        // 128 j * 64 d                         = 8192
#define OFF_PW2T 46080        // 64*64                                = 4096
#define OFF_UI   50176        // 256
#define OFF_AI   50432        // 64
#define OFF_PB1  50496        // 64
#define OFF_PB2  50560        // 64
#define OFF_RED  50624        // 1024
#define SMEM_FLOATS 51648
#define SMEM_BYTES  (SMEM_FLOATS*4)

__global__ void __launch_bounds__(512, 1)
pt_layer_main(const float* __restrict__ pm_b1,
              const float* __restrict__ pm_b2,
              float* __restrict__ out) {
    extern __shared__ float sm[];
    float* sH1Td = sm + OFF_H1TD;
    float* sH1   = sm + OFF_H1;
    float* sH2   = sm + OFF_H2;
    float* sSIM  = sm + OFF_SIM;
    float* sVP   = sm + OFF_VP;
    float* sPW2T = sm + OFF_PW2T;
    float* sUi   = sm + OFF_UI;
    float* sAi   = sm + OFF_AI;
    float* sPB1  = sm + OFF_PB1;
    float* sPB2  = sm + OFF_PB2;
    float* sRed  = sm + OFF_RED;

    int t  = threadIdx.x;
    int bt = blockIdx.x >> 7;
    int i  = blockIdx.x & 127;
    size_t ptbase = (size_t)bt * NPTS;

    // ---- phase 0: small loads ----
    if (t < 256)                 sUi[t]      = g_U[(ptbase + i)*AH + t] + g_cc[t];
    else if (t < 320)            sAi[t-256]  = g_A[(ptbase + i)*DIM + (t-256)];
    else if (t < 384)            sPB1[t-320] = pm_b1[t-320];
    else if (t < 448)            sPB2[t-384] = pm_b2[t-384];
    for (int idx = t; idx < (PH*DIM)/4; idx += 512)
        ((float4*)sPW2T)[idx] = ((const float4*)g_PW2T)[idx];

    for (int jt = 0; jt < 2; jt++) {
        int j0 = jt * JT;
        __syncthreads();   // prev tile consumers done (and phase-0 for jt==0)

        // ---- (a) H1 construction: relu(a_i - a_j + b1) ----
        {
            int jj = t & 63;
            int hb = (t >> 6) * 8;
            const float* ap = &g_A[(ptbase + j0 + jj)*DIM + hb];
            float4 a0 = *(const float4*)ap;
            float4 a1 = *(const float4*)(ap + 4);
            float av[8] = {a0.x,a0.y,a0.z,a0.w,a1.x,a1.y,a1.z,a1.w};
            float hv[8];
#pragma unroll
            for (int q = 0; q < 8; q++)
                hv[q] = fmaxf(sAi[hb+q] - av[q] + sPB1[hb+q], 0.f);
#pragma unroll
            for (int q = 0; q < 8; q++)          // duplicated layout for GEMM1
                *(u64*)&sH1Td[(hb+q)*136 + jj*2] = pk2(hv[q]);
            *(float4*)&sH1[jj*68 + hb]     = make_float4(hv[0],hv[1],hv[2],hv[3]);
            *(float4*)&sH1[jj*68 + hb + 4] = make_float4(hv[4],hv[5],hv[6],hv[7]);
        }
        __syncthreads();

        // ---- (b) GEMM1: Z1[64][256] = H1 @ Wc.T + (U_i + cc - WK_j), relu -> sH2
        {
            int tr = t >> 5;          // 0..15 -> 4 rows each
            int tc = t & 31;          // -> m = tc*8..+7 (4 packed pairs)
            u64 acc[4][4];
            ulonglong2 ua = *(const ulonglong2*)&sUi[tc*8];
            ulonglong2 ub = *(const ulonglong2*)&sUi[tc*8 + 4];
            u64 ui[4] = {ua.x, ua.y, ub.x, ub.y};
            u64 m1 = pk2(-1.0f);
            const float* wkbase = g_WK + (ptbase + j0 + tr*4)*AH + tc*8;
#pragma unroll
            for (int r = 0; r < 4; r++) {
                ulonglong2 ka = *(const ulonglong2*)(wkbase + r*AH);
                ulonglong2 kb = *(const ulonglong2*)(wkbase + r*AH + 4);
                u64 kk[4] = {ka.x, ka.y, kb.x, kb.y};
#pragma unroll
                for (int c = 0; c < 4; c++) {
                    acc[r][c] = ui[c];
                    fm2(acc[r][c], kk[c], m1);   // ui - wk
                }
            }
            const float* h1b = &sH1Td[tr*8];
            const float* wcb = &g_WcT[tc*8];
#pragma unroll 4
            for (int k = 0; k < PH; k++) {
                ulonglong2 h0 = *(const ulonglong2*)(h1b + k*136);
                ulonglong2 h1 = *(const ulonglong2*)(h1b + k*136 + 4);
                u64 hh[4] = {h0.x, h0.y, h1.x, h1.y};   // already {v,v}
                ulonglong2 wa = *(const ulonglong2*)(wcb + k*AH);
                ulonglong2 wb = *(const ulonglong2*)(wcb + k*AH + 4);
                u64 ww[4] = {wa.x, wa.y, wb.x, wb.y};
#pragma unroll
                for (int r = 0; r < 4; r++)
#pragma unroll
                    for (int c = 0; c < 4; c++) fm2(acc[r][c], hh[r], ww[c]);
            }
#pragma unroll
            for (int r = 0; r < 4; r++) {
                float2 p0 = up2(acc[r][0]), p1 = up2(acc[r][1]);
                float2 p2 = up2(acc[r][2]), p3 = up2(acc[r][3]);
                float* dst = &sH2[(tr*4 + r)*260 + tc*8];
                *(float4*)dst = make_float4(fmaxf(p0.x,0.f), fmaxf(p0.y,0.f),
                                            fmaxf(p1.x,0.f), fmaxf(p1.y,0.f));
                *(float4*)(dst+4) = make_float4(fmaxf(p2.x,0.f), fmaxf(p2.y,0.f),
                                                fmaxf(p3.x,0.f), fmaxf(p3.y,0.f));
            }
        }
        __syncthreads();

        // ---- (c) GEMM2: SIM[64][64] = H2 @ am_w2.T  (am_b2 dropped: softmax-invariant)
        {
            int j = t >> 3, d0 = (t & 7) * 8;
            u64 a2[4] = {0ull, 0ull, 0ull, 0ull};
            const float* hb = &sH2[j*260];
            const float* wb = g_AMW2T + d0;
#pragma unroll 8
            for (int k = 0; k < AH; k++) {
                u64 hh = pk2(hb[k]);
                ulonglong2 w0 = *(const ulonglong2*)(wb + k*DIM);
                ulonglong2 w1 = *(const ulonglong2*)(wb + k*DIM + 4);
                fm2(a2[0], hh, w0.x); fm2(a2[1], hh, w0.y);
                fm2(a2[2], hh, w1.x); fm2(a2[3], hh, w1.y);
            }
            float2 p0 = up2(a2[0]), p1 = up2(a2[1]), p2 = up2(a2[2]), p3 = up2(a2[3]);
            float* dst = &sSIM[(j0 + j)*DIM + d0];
            *(float4*)dst     = make_float4(p0.x, p0.y, p1.x, p1.y);
            *(float4*)(dst+4) = make_float4(p2.x, p2.y, p3.x, p3.y);
        }

        // ---- (d) VP[64][64] = H1 @ pm_w2.T + pm_b2 + V  (reads sH1, stable) ----
        {
            int j = t >> 3, d0 = (t & 7) * 8;
            ulonglong2 b0 = *(const ulonglong2*)&sPB2[d0];
            ulonglong2 b1 = *(const ulonglong2*)&sPB2[d0 + 4];
            u64 a3[4] = {b0.x, b0.y, b1.x, b1.y};
            const float* hb = &sH1[j*68];
            const float* wb = sPW2T + d0;
#pragma unroll 8
            for (int k = 0; k < PH; k++) {
                u64 hh = pk2(hb[k]);
                ulonglong2 w0 = *(const ulonglong2*)(wb + k*DIM);
                ulonglong2 w1 = *(const ulonglong2*)(wb + k*DIM + 4);
                fm2(a3[0], hh, w0.x); fm2(a3[1], hh, w0.y);
                fm2(a3[2], hh, w1.x); fm2(a3[3], hh, w1.y);
            }
            const float* vp = &g_V[(ptbase + j0 + j)*DIM + d0];
            float4 v0 = *(const float4*)vp;
            float4 v1 = *(const float4*)(vp + 4);
            float2 p0 = up2(a3[0]), p1 = up2(a3[1]), p2 = up2(a3[2]), p3 = up2(a3[3]);
            float* dst = &sVP[(j0 + j)*DIM + d0];
            *(float4*)dst     = make_float4(p0.x+v0.x, p0.y+v0.y, p1.x+v0.z, p1.y+v0.w);
            *(float4*)(dst+4) = make_float4(p2.x+v1.x, p2.y+v1.y, p3.x+v1.z, p3.y+v1.w);
        }
    }
    __syncthreads();

    // ---- softmax over j + aggregate ----
    {
        int d = t & 63;
        int g = t >> 6;              // 8 groups of 16 rows
        int jlo = g * 16;
        float mx = -1e30f;
        for (int j = jlo; j < jlo + 16; j++) mx = fmaxf(mx, sSIM[j*DIM + d]);
        sRed[g*64 + d] = mx;
        __syncthreads();
#pragma unroll
        for (int gg = 0; gg < 8; gg++) mx = fmaxf(mx, sRed[gg*64 + d]);

        float se = 0.f, sa = 0.f;
        for (int j = jlo; j < jlo + 16; j++) {
            float e = __expf(sSIM[j*DIM + d] - mx);
            se += e;
            sa  = fmaf(e, sVP[j*DIM + d], sa);
        }
        __syncthreads();
        sRed[g*64 + d]       = se;
        sRed[512 + g*64 + d] = sa;
        __syncthreads();
        if (g == 0) {
            float S = 0.f, Ag = 0.f;
#pragma unroll
            for (int gg = 0; gg < 8; gg++) {
                S  += sRed[gg*64 + d];
                Ag += sRed[512 + gg*64 + d];
            }
            out[(ptbase + i)*DIM + d] = Ag / S;
        }
    }
}

// ---------------- launch ----------------
extern "C" void kernel_launch(void* const* d_in, const int* in_sizes, int n_in,
                              void* d_out, int out_size) {
    const float* x      = (const float*)d_in[0];
    const float* pos    = (const float*)d_in[1];
    const float* w_qkv  = (const float*)d_in[2];
    const float* pm_w1  = (const float*)d_in[3];
    const float* pm_b1  = (const float*)d_in[4];
    const float* pm_w2  = (const float*)d_in[5];
    const float* pm_b2  = (const float*)d_in[6];
    const float* am_w1  = (const float*)d_in[7];
    const float* am_b1  = (const float*)d_in[8];
    const float* am_w2  = (const float*)d_in[9];
    // am_b2 (d_in[10]) intentionally unused: constant over softmax axis
    float* out = (float*)d_out;

    cudaFuncSetAttribute(pt_layer_main,
                         cudaFuncAttributeMaxDynamicSharedMemorySize, SMEM_BYTES);

    prep_weights<<<70, 256>>>(pm_w2, am_w1, am_b1, pm_b2, am_w2);
    prep_points <<<BT*NPTS, 128>>>(x, pos, w_qkv, pm_w1, am_w1);
    pt_layer_main<<<BT*NPTS, 512, SMEM_BYTES>>>(pm_b1, pm_b2, out);
}

// round 6
// speedup vs baseline: 2.0471x; 2.0471x over previous
#include <cuda_runtime.h>
#include <cuda_bf16.h>

#define BT   32
#define NPTS 128
#define DIM  64
#define AH   256   // ATTN_HID
#define PH   64    // POS_HID
#define PIN  34

// ---------------- device scratch ----------------
__device__ float g_A [BT*NPTS*DIM];   // p @ pm_w1.T
__device__ float g_U [BT*NPTS*AH];    // q @ am_w1.T
__device__ float g_WK[BT*NPTS*AH];    // k @ am_w1.T
__device__ float g_V [BT*NPTS*DIM];   // v
__device__ float g_WcT  [PH*AH];      // [h][m]
__device__ float g_AMW2T[AH*DIM];     // [m][d]
__device__ float g_PW2T [PH*DIM];     // [h][d]
__device__ float g_cc   [AH];         // am_b1 + pm_b2 @ am_w1.T

// ---------------- kernel 0: weight-derived tensors ----------------
__global__ void prep_weights(const float* __restrict__ pm_w2,
                             const float* __restrict__ am_w1,
                             const float* __restrict__ am_b1,
                             const float* __restrict__ pm_b2,
                             const float* __restrict__ am_w2) {
    int b = blockIdx.x, t = threadIdx.x;
    if (b < 64) {                       // WcT[h][m] = dot(am_w1[m], pm_w2[:,h])
        int gid = b * 256 + t;
        int m = gid >> 6, h = gid & 63;
        float s = 0.f;
#pragma unroll 8
        for (int d = 0; d < DIM; d++) s += am_w1[m*DIM + d] * pm_w2[d*PH + h];
        g_WcT[h*AH + m] = s;
    } else if (b < 68) {                // AMW2T transpose [m][d]
        for (int i = (b-64)*256 + t; i < AH*DIM; i += 4*256) {
            int m = i >> 6, d = i & 63;
            g_AMW2T[m*DIM + d] = am_w2[d*AH + m];
        }
    } else if (b == 68) {               // PW2T transpose [h][d]
        for (int i = t; i < PH*DIM; i += 256) {
            int h = i >> 6, d = i & 63;
            g_PW2T[h*DIM + d] = pm_w2[d*PH + h];
        }
    } else {                            // cc
        int m = t;
        float s = am_b1[m];
#pragma unroll 8
        for (int d = 0; d < DIM; d++) s += pm_b2[d] * am_w1[m*DIM + d];
        g_cc[m] = s;
    }
}

// ---------------- kernel 1: per-point precompute ----------------
__global__ void prep_points(const float* __restrict__ x,
                            const float* __restrict__ pos,
                            const float* __restrict__ w_qkv,
                            const float* __restrict__ pm_w1,
                            const float* __restrict__ am_w1) {
    __shared__ float sx[DIM], sp[PIN], sq[DIM], sk[DIM];
    int pt = blockIdx.x;            // bt*128 + n
    int bt = pt >> 7, n = pt & 127;
    int t  = threadIdx.x;           // 128 threads

    if (t < DIM) sx[t] = x[(size_t)pt*DIM + t];
    if (t < PIN) {
        int c = t / 17, j = t % 17;
        sp[t] = pos[(((size_t)bt*17 + j)*3 + c)*NPTS + n];
    }
    __syncthreads();

    for (int m = t; m < 3*DIM; m += 128) {
        const float4* wr = (const float4*)(w_qkv + m*DIM);
        float s = 0.f;
#pragma unroll
        for (int i = 0; i < DIM/4; i++) {
            float4 w  = wr[i];
            float4 xv = ((const float4*)sx)[i];
            s += w.x*xv.x + w.y*xv.y + w.z*xv.z + w.w*xv.w;
        }
        if      (m <   DIM) sq[m]        = s;
        else if (m < 2*DIM) sk[m-DIM]    = s;
        else g_V[(size_t)pt*DIM + (m-2*DIM)] = s;
    }
    if (t < DIM) {
        const float* wr = pm_w1 + t*PIN;
        float s = 0.f;
#pragma unroll
        for (int f = 0; f < PIN; f++) s += sp[f]*wr[f];
        g_A[(size_t)pt*DIM + t] = s;
    }
    __syncthreads();
    for (int m = t; m < AH; m += 128) {
        const float4* wr = (const float4*)(am_w1 + m*DIM);
        float su = 0.f, sw = 0.f;
#pragma unroll
        for (int i = 0; i < DIM/4; i++) {
            float4 w  = wr[i];
            float4 qv = ((const float4*)sq)[i];
            float4 kv = ((const float4*)sk)[i];
            su += w.x*qv.x + w.y*qv.y + w.z*qv.z + w.w*qv.w;
            sw += w.x*kv.x + w.y*kv.y + w.z*kv.z + w.w*kv.w;
        }
        g_U [(size_t)pt*AH + m] = su;
        g_WK[(size_t)pt*AH + m] = sw;
    }
}

// ---------------- kernel 2: fused pairwise MLPs + online softmax ------------
// Block = one (bt, i). 256 threads. j in 4 tiles of 32. ALL weights in smem.
#define S_WCT 0            // [64 k][256 m]        = 16384
#define S_W2T 16384        // [256 k][64 d]        = 16384
#define S_PW2 32768        // [64 k][64 d]         = 4096
#define S_H1T 36864        // [64 h][36 j pad]     = 2304
#define S_H2  39168        // [32 j][264 pad]      = 8448
#define S_SIM 47616        // [32 j][64 d]         = 2048
#define S_VP  49664        // [32 j][64 d]         = 2048
#define S_UI  51712        // 256
#define S_AI  51968        // 64
#define S_PB1 52032        // 64
#define S_PB2 52096        // 64
#define S_MAX 52160        // 64 running max
#define S_SUM 52224        // 64 running sum
#define S_AGG 52288        // 64 running agg
#define S_RM  52352        // 4*64 partial max
#define S_RS  52608        // 4*64 partial sum
#define S_RA  52864        // 4*64 partial agg
#define SMEM_FLOATS 53120
#define SMEM_BYTES  (SMEM_FLOATS*4)

__global__ void __launch_bounds__(256, 1)
pt_main(const float* __restrict__ pm_b1,
        const float* __restrict__ pm_b2,
        float* __restrict__ out) {
    extern __shared__ float sm[];
    int t  = threadIdx.x;
    int bt = blockIdx.x >> 7;
    int i  = blockIdx.x & 127;
    size_t pb = (size_t)bt * NPTS;

    // ---- load weights + per-i state into smem ----
    for (int idx = t; idx < (PH*AH)/4; idx += 256)
        ((float4*)(sm+S_WCT))[idx] = ((const float4*)g_WcT)[idx];
    for (int idx = t; idx < (AH*DIM)/4; idx += 256)
        ((float4*)(sm+S_W2T))[idx] = ((const float4*)g_AMW2T)[idx];
    for (int idx = t; idx < (PH*DIM)/4; idx += 256)
        ((float4*)(sm+S_PW2))[idx] = ((const float4*)g_PW2T)[idx];
    sm[S_UI + t] = g_U[(pb + i)*AH + t] + g_cc[t];
    if (t < DIM) {
        sm[S_AI  + t] = g_A[(pb + i)*DIM + t];
        sm[S_PB1 + t] = pm_b1[t];
        sm[S_PB2 + t] = pm_b2[t];
        sm[S_MAX + t] = -1e30f;
        sm[S_SUM + t] = 0.f;
        sm[S_AGG + t] = 0.f;
    }

    int tr = t >> 5;      // warp id 0..7
    int tc = t & 31;      // lane

    for (int jt = 0; jt < 4; jt++) {
        int j0 = jt * 32;
        __syncthreads();   // (A) prior tile fully consumed / initial load done

        // ---- H1T[h][j] = relu(a_i - a_j + pm_b1) ; warp tr owns h = tr*8..+7, lane = j
        {
            int jj = tc;
            const float* ap = &g_A[(pb + j0 + jj)*DIM + tr*8];
            float4 a0 = *(const float4*)ap;
            float4 a1 = *(const float4*)(ap + 4);
            float av[8] = {a0.x,a0.y,a0.z,a0.w,a1.x,a1.y,a1.z,a1.w};
#pragma unroll
            for (int q = 0; q < 8; q++) {
                int h = tr*8 + q;
                sm[S_H1T + h*36 + jj] =
                    fmaxf(sm[S_AI + h] - av[q] + sm[S_PB1 + h], 0.f);
            }
        }
        __syncthreads();   // (B)

        // ---- GEMM1: Z1[32 j][256 m] = H1 @ WcT + (U_i + cc - WK_j), relu -> H2
        // thread: rows jj = tr*4..+3 ; m-chunks [tc*4..+3] and [128+tc*4..+3]
        {
            float acc[4][8];
            float4 u0 = *(const float4*)&sm[S_UI + tc*4];
            float4 u1 = *(const float4*)&sm[S_UI + 128 + tc*4];
            float ui[8] = {u0.x,u0.y,u0.z,u0.w,u1.x,u1.y,u1.z,u1.w};
#pragma unroll
            for (int r = 0; r < 4; r++) {
                const float* wkb = &g_WK[(pb + j0 + tr*4 + r)*AH];
                float4 k0 = *(const float4*)(wkb + tc*4);
                float4 k1 = *(const float4*)(wkb + 128 + tc*4);
                acc[r][0]=ui[0]-k0.x; acc[r][1]=ui[1]-k0.y;
                acc[r][2]=ui[2]-k0.z; acc[r][3]=ui[3]-k0.w;
                acc[r][4]=ui[4]-k1.x; acc[r][5]=ui[5]-k1.y;
                acc[r][6]=ui[6]-k1.z; acc[r][7]=ui[7]-k1.w;
            }
#pragma unroll 2
            for (int k = 0; k < PH; k++) {
                float4 hv = *(const float4*)&sm[S_H1T + k*36 + tr*4];   // bcast
                float4 w0 = *(const float4*)&sm[S_WCT + k*AH + tc*4];   // contig
                float4 w1 = *(const float4*)&sm[S_WCT + k*AH + 128 + tc*4];
                float hr[4] = {hv.x,hv.y,hv.z,hv.w};
                float wc[8] = {w0.x,w0.y,w0.z,w0.w,w1.x,w1.y,w1.z,w1.w};
#pragma unroll
                for (int r = 0; r < 4; r++)
#pragma unroll
                    for (int c = 0; c < 8; c++)
                        acc[r][c] = fmaf(hr[r], wc[c], acc[r][c]);
            }
#pragma unroll
            for (int r = 0; r < 4; r++) {
                float* dst = &sm[S_H2 + (tr*4 + r)*264];
                *(float4*)(dst + tc*4) =
                    make_float4(fmaxf(acc[r][0],0.f), fmaxf(acc[r][1],0.f),
                                fmaxf(acc[r][2],0.f), fmaxf(acc[r][3],0.f));
                *(float4*)(dst + 128 + tc*4) =
                    make_float4(fmaxf(acc[r][4],0.f), fmaxf(acc[r][5],0.f),
                                fmaxf(acc[r][6],0.f), fmaxf(acc[r][7],0.f));
            }
        }
        __syncthreads();   // (C)

        // ---- GEMM2: SIM[32 j][64 d] = H2 @ W2T  (am_b2 softmax-invariant, dropped)
        // thread: rows jj = tr*4..+3 ; d = tc*2, tc*2+1 ; k unrolled by 4 (float4 bcast)
        {
            float a2[4][2] = {};
            const float* h0p = &sm[S_H2 + (tr*4+0)*264];
            const float* h1p = &sm[S_H2 + (tr*4+1)*264];
            const float* h2p = &sm[S_H2 + (tr*4+2)*264];
            const float* h3p = &sm[S_H2 + (tr*4+3)*264];
#pragma unroll 2
            for (int k = 0; k < AH; k += 4) {
                float4 h0 = *(const float4*)(h0p + k);
                float4 h1 = *(const float4*)(h1p + k);
                float4 h2 = *(const float4*)(h2p + k);
                float4 h3 = *(const float4*)(h3p + k);
                float hh[4][4] = {{h0.x,h0.y,h0.z,h0.w},{h1.x,h1.y,h1.z,h1.w},
                                  {h2.x,h2.y,h2.z,h2.w},{h3.x,h3.y,h3.z,h3.w}};
#pragma unroll
                for (int s = 0; s < 4; s++) {
                    float2 wv = *(const float2*)&sm[S_W2T + (k+s)*DIM + tc*2];
#pragma unroll
                    for (int r = 0; r < 4; r++) {
                        a2[r][0] = fmaf(hh[r][s], wv.x, a2[r][0]);
                        a2[r][1] = fmaf(hh[r][s], wv.y, a2[r][1]);
                    }
                }
            }
#pragma unroll
            for (int r = 0; r < 4; r++)
                *(float2*)&sm[S_SIM + (tr*4+r)*64 + tc*2] =
                    make_float2(a2[r][0], a2[r][1]);
        }

        // ---- VP[32 j][64 d] = H1 @ PW2T + pm_b2 + V_j  (reads H1T transposed)
        {
            float b0 = sm[S_PB2 + tc*2], b1 = sm[S_PB2 + tc*2 + 1];
            float a3[4][2] = {{b0,b1},{b0,b1},{b0,b1},{b0,b1}};
#pragma unroll 2
            for (int k = 0; k < PH; k++) {
                float4 hv = *(const float4*)&sm[S_H1T + k*36 + tr*4];   // bcast
                float2 wv = *(const float2*)&sm[S_PW2 + k*DIM + tc*2];
                float hr[4] = {hv.x,hv.y,hv.z,hv.w};
#pragma unroll
                for (int r = 0; r < 4; r++) {
                    a3[r][0] = fmaf(hr[r], wv.x, a3[r][0]);
                    a3[r][1] = fmaf(hr[r], wv.y, a3[r][1]);
                }
            }
#pragma unroll
            for (int r = 0; r < 4; r++) {
                float2 v = *(const float2*)&g_V[(pb + j0 + tr*4 + r)*DIM + tc*2];
                *(float2*)&sm[S_VP + (tr*4+r)*64 + tc*2] =
                    make_float2(a3[r][0] + v.x, a3[r][1] + v.y);
            }
        }
        __syncthreads();   // (D)

        // ---- online softmax update over this tile ----
        {
            int d = t & 63;
            int g = t >> 6;              // 4 groups × 8 j
            int jl = g * 8;
            float pmx = -1e30f;
            for (int j = jl; j < jl+8; j++)
                pmx = fmaxf(pmx, sm[S_SIM + j*64 + d]);
            sm[S_RM + g*64 + d] = pmx;
            __syncthreads();   // (E)
            float nm = sm[S_MAX + d];    // read-only here; updated only at (F)
            nm = fmaxf(nm, sm[S_RM       + d]);
            nm = fmaxf(nm, sm[S_RM + 64  + d]);
            nm = fmaxf(nm, sm[S_RM + 128 + d]);
            nm = fmaxf(nm, sm[S_RM + 192 + d]);
            float ps = 0.f, pa = 0.f;
            for (int j = jl; j < jl+8; j++) {
                float e = __expf(sm[S_SIM + j*64 + d] - nm);
                ps += e;
                pa  = fmaf(e, sm[S_VP + j*64 + d], pa);
            }
            sm[S_RS + g*64 + d] = ps;
            sm[S_RA + g*64 + d] = pa;
            __syncthreads();   // (F)
            if (t < 64) {
                float om  = sm[S_MAX + d];
                float nm2 = om;
                nm2 = fmaxf(nm2, sm[S_RM       + d]);
                nm2 = fmaxf(nm2, sm[S_RM + 64  + d]);
                nm2 = fmaxf(nm2, sm[S_RM + 128 + d]);
                nm2 = fmaxf(nm2, sm[S_RM + 192 + d]);
                float sc = __expf(om - nm2);
                sm[S_SUM + d] = sm[S_SUM + d]*sc
                    + sm[S_RS+d] + sm[S_RS+64+d] + sm[S_RS+128+d] + sm[S_RS+192+d];
                sm[S_AGG + d] = sm[S_AGG + d]*sc
                    + sm[S_RA+d] + sm[S_RA+64+d] + sm[S_RA+128+d] + sm[S_RA+192+d];
                sm[S_MAX + d] = nm2;
            }
        }
    }
    __syncthreads();
    if (t < 64)
        out[(pb + i)*DIM + t] = sm[S_AGG + t] / sm[S_SUM + t];
}

// ---------------- launch ----------------
extern "C" void kernel_launch(void* const* d_in, const int* in_sizes, int n_in,
                              void* d_out, int out_size) {
    const float* x      = (const float*)d_in[0];
    const float* pos    = (const float*)d_in[1];
    const float* w_qkv  = (const float*)d_in[2];
    const float* pm_w1  = (const float*)d_in[3];
    const float* pm_b1  = (const float*)d_in[4];
    const float* pm_w2  = (const float*)d_in[5];
    const float* pm_b2  = (const float*)d_in[6];
    const float* am_w1  = (const float*)d_in[7];
    const float* am_b1  = (const float*)d_in[8];
    const float* am_w2  = (const float*)d_in[9];
    // am_b2 (d_in[10]) unused: constant over softmax axis
    float* out = (float*)d_out;

    cudaFuncSetAttribute(pt_main,
                         cudaFuncAttributeMaxDynamicSharedMemorySize, SMEM_BYTES);

    prep_weights<<<70, 256>>>(pm_w2, am_w1, am_b1, pm_b2, am_w2);
    prep_points <<<BT*NPTS, 128>>>(x, pos, w_qkv, pm_w1, am_w1);
    pt_main     <<<BT*NPTS, 256, SMEM_BYTES>>>(pm_b1, pm_b2, out);
}

// round 9
// speedup vs baseline: 3.3349x; 1.6291x over previous
#include <cuda_runtime.h>
#include <cuda_bf16.h>
#include <cstdint>

#define BT   32
#define NPTS 128
#define DIM  64
#define AH   256
#define PH   64
#define PIN  34

// ---------------- tf32 helpers ----------------
__device__ __forceinline__ float tf32r(float x) {
    uint32_t u;
    asm("cvt.rna.tf32.f32 %0, %1;" : "=r"(u) : "f"(x));
    return __uint_as_float(u);
}
__device__ __forceinline__ void mma8(float c[4], const uint32_t a[4], const uint32_t b[2]) {
    asm volatile(
        "mma.sync.aligned.m16n8k8.row.col.f32.tf32.tf32.f32 "
        "{%0,%1,%2,%3},{%4,%5,%6,%7},{%8,%9},{%0,%1,%2,%3};"
        : "+f"(c[0]), "+f"(c[1]), "+f"(c[2]), "+f"(c[3])
        : "r"(a[0]), "r"(a[1]), "r"(a[2]), "r"(a[3]), "r"(b[0]), "r"(b[1]));
}

// ---------------- device scratch ----------------
__device__ float g_A [BT*NPTS*DIM];   // p @ pm_w1.T            (fp32)
__device__ float g_U [BT*NPTS*AH];    // q @ am_w1.T            (fp32)
__device__ float g_WK[BT*NPTS*AH];    // k @ am_w1.T            (fp32)
__device__ float g_V [BT*NPTS*DIM];   // v                      (fp32)
__device__ float g_WcI [256*68];      // Wc[m][h], stride 68, tf32-rounded
__device__ float g_W2I [64*260];      // am_w2[d][m], stride 260, tf32-rounded
__device__ float g_PW2I[64*68];       // pm_w2[d][h], stride 68, tf32-rounded
__device__ float g_cc  [AH];          // am_b1 + pm_b2 @ am_w1.T (fp32)

// ---------------- kernel 0: weight-derived images ----------------
__global__ void prep_weights(const float* __restrict__ pm_w2,
                             const float* __restrict__ am_w1,
                             const float* __restrict__ am_b1,
                             const float* __restrict__ pm_b2,
                             const float* __restrict__ am_w2) {
    int b = blockIdx.x, t = threadIdx.x;
    if (b < 64) {                       // Wc[m][h] = dot(am_w1[m,:], pm_w2[:,h])
        int gid = b * 256 + t;
        int m = gid >> 6, h = gid & 63;
        float s = 0.f;
#pragma unroll 8
        for (int d = 0; d < DIM; d++) s += am_w1[m*DIM + d] * pm_w2[d*PH + h];
        g_WcI[m*68 + h] = tf32r(s);
    } else if (b < 68) {                // W2 image [d][m] stride 260
        for (int i = (b-64)*4096 + t; i < (b-63)*4096; i += 256) {
            int d = i >> 8, m = i & 255;
            g_W2I[d*260 + m] = tf32r(am_w2[i]);
        }
    } else if (b == 68) {               // PW2 image [d][h] stride 68
        for (int i = t; i < 64*64; i += 256) {
            int d = i >> 6, h = i & 63;
            g_PW2I[d*68 + h] = tf32r(pm_w2[i]);
        }
    } else {                            // cc
        int m = t;
        float s = am_b1[m];
#pragma unroll 8
        for (int d = 0; d < DIM; d++) s += pm_b2[d] * am_w1[m*DIM + d];
        g_cc[m] = s;
    }
}

// ---------------- kernel 1: per-point precompute (validated) ----------------
__global__ void prep_points(const float* __restrict__ x,
                            const float* __restrict__ pos,
                            const float* __restrict__ w_qkv,
                            const float* __restrict__ pm_w1,
                            const float* __restrict__ am_w1) {
    __shared__ float sx[DIM], sp[PIN], sq[DIM], sk[DIM];
    int pt = blockIdx.x;
    int bt = pt >> 7, n = pt & 127;
    int t  = threadIdx.x;

    if (t < DIM) sx[t] = x[(size_t)pt*DIM + t];
    if (t < PIN) {
        int c = t / 17, j = t % 17;
        sp[t] = pos[(((size_t)bt*17 + j)*3 + c)*NPTS + n];
    }
    __syncthreads();
    for (int m = t; m < 3*DIM; m += 128) {
        const float4* wr = (const float4*)(w_qkv + m*DIM);
        float s = 0.f;
#pragma unroll
        for (int i = 0; i < DIM/4; i++) {
            float4 w  = wr[i];
            float4 xv = ((const float4*)sx)[i];
            s += w.x*xv.x + w.y*xv.y + w.z*xv.z + w.w*xv.w;
        }
        if      (m <   DIM) sq[m]     = s;
        else if (m < 2*DIM) sk[m-DIM] = s;
        else g_V[(size_t)pt*DIM + (m-2*DIM)] = s;
    }
    if (t < DIM) {
        const float* wr = pm_w1 + t*PIN;
        float s = 0.f;
#pragma unroll
        for (int f = 0; f < PIN; f++) s += sp[f]*wr[f];
        g_A[(size_t)pt*DIM + t] = s;
    }
    __syncthreads();
    for (int m = t; m < AH; m += 128) {
        const float4* wr = (const float4*)(am_w1 + m*DIM);
        float su = 0.f, sw = 0.f;
#pragma unroll
        for (int i = 0; i < DIM/4; i++) {
            float4 w  = wr[i];
            float4 qv = ((const float4*)sq)[i];
            float4 kv = ((const float4*)sk)[i];
            su += w.x*qv.x + w.y*qv.y + w.z*qv.z + w.w*qv.w;
            sw += w.x*kv.x + w.y*kv.y + w.z*kv.z + w.w*kv.w;
        }
        g_U [(size_t)pt*AH + m] = su;
        g_WK[(size_t)pt*AH + m] = sw;
    }
}

// ---------------- kernel 2: warp-MMA fused layer ----------------
// Block = (bt, 4 i's). 256 threads = 8 warps. Warp grid 4(j) x 2(n).
// smem float offsets
#define S_WC   0          // 256*68 = 17408
#define S_W2   17408      // 64*260 = 16640
#define S_PW2  34048      // 64*68  = 4352
#define S_H1   38400      // 128*68 = 8704   (later holds VP)
#define S_Z    47104      // 128*68 = 8704   (later holds SIM)
#define S_UIC  55808      // 256
#define S_AI   56064      // 64
#define S_PB1  56128      // 64
#define S_PB2  56192      // 64
#define S_RED  56256      // 512
#define SMEM_FLOATS 56768
#define SMEM_BYTES  (SMEM_FLOATS*4)

__global__ void __launch_bounds__(256, 1)
pt_mma(const float* __restrict__ pm_b1,
       const float* __restrict__ pm_b2,
       float* __restrict__ out) {
    extern __shared__ float sm[];
    int t    = threadIdx.x;
    int wid  = t >> 5, lane = t & 31;
    int g    = lane >> 2, tk = lane & 3;
    int wj   = wid >> 1;          // 0..3 : j-warp
    int wm   = wid & 1;           // 0..1 : n-warp
    int jb   = wj * 32;
    int nb   = wm * 32;
    int bt   = blockIdx.x >> 5;
    int i0   = (blockIdx.x & 31) * 4;
    size_t pb = (size_t)bt * NPTS;

    // ---- load weight images + biases ----
    for (int idx = t; idx < (256*68)/4; idx += 256)
        ((float4*)(sm+S_WC))[idx] = ((const float4*)g_WcI)[idx];
    for (int idx = t; idx < (64*260)/4; idx += 256)
        ((float4*)(sm+S_W2))[idx] = ((const float4*)g_W2I)[idx];
    for (int idx = t; idx < (64*68)/4; idx += 256)
        ((float4*)(sm+S_PW2))[idx] = ((const float4*)g_PW2I)[idx];
    if (t < DIM) { sm[S_PB1+t] = pm_b1[t]; sm[S_PB2+t] = pm_b2[t]; }

    for (int ii = 0; ii < 4; ii++) {
        int i = i0 + ii;
        __syncthreads();                       // weights / prev-i consumers done
        sm[S_UIC + t] = g_U[(pb + i)*AH + t] + g_cc[t];
        if (t < 64) sm[S_AI + t] = g_A[(pb + i)*DIM + t];
        __syncthreads();

        // ---- H1[j][h] = tf32(relu(a_i - a_j + pm_b1)), stride 68 ----
        {
            int j  = t >> 1;
            int h0 = (t & 1) * 32;
            const float4* ap = (const float4*)(g_A + (pb + j)*DIM + h0);
#pragma unroll
            for (int q = 0; q < 8; q++) {
                float4 a = ap[q];
                int hh = h0 + q*4;
                float4 v;
                v.x = tf32r(fmaxf(sm[S_AI+hh  ] - a.x + sm[S_PB1+hh  ], 0.f));
                v.y = tf32r(fmaxf(sm[S_AI+hh+1] - a.y + sm[S_PB1+hh+1], 0.f));
                v.z = tf32r(fmaxf(sm[S_AI+hh+2] - a.z + sm[S_PB1+hh+2], 0.f));
                v.w = tf32r(fmaxf(sm[S_AI+hh+3] - a.w + sm[S_PB1+hh+3], 0.f));
                *(float4*)&sm[S_H1 + j*68 + hh] = v;
            }
        }
        __syncthreads();

        // ---- chunked GEMM1 -> relu -> Z -> GEMM2 accumulate ----
        float c2[2][4][4] = {};                // persistent SIM accums
        for (int ch = 0; ch < 4; ch++) {
            // GEMM1: C1[j, m(64 of chunk)] = H1 @ Wc[chunk]^T
            float c1[2][4][4] = {};
#pragma unroll
            for (int s = 0; s < 8; s++) {
                int k0 = s*8;
                uint32_t a[2][4], b[4][2];
#pragma unroll
                for (int jt = 0; jt < 2; jt++) {
                    const float* p = sm + S_H1 + (jb + jt*16)*68 + k0;
                    a[jt][0] = __float_as_uint(p[ g*68      + tk  ]);
                    a[jt][1] = __float_as_uint(p[(g+8)*68   + tk  ]);
                    a[jt][2] = __float_as_uint(p[ g*68      + tk+4]);
                    a[jt][3] = __float_as_uint(p[(g+8)*68   + tk+4]);
                }
#pragma unroll
                for (int nt = 0; nt < 4; nt++) {
                    const float* p = sm + S_WC + (ch*64 + nb + nt*8 + g)*68 + k0;
                    b[nt][0] = __float_as_uint(p[tk]);
                    b[nt][1] = __float_as_uint(p[tk+4]);
                }
#pragma unroll
                for (int jt = 0; jt < 2; jt++)
#pragma unroll
                    for (int nt = 0; nt < 4; nt++) mma8(c1[jt][nt], a[jt], b[nt]);
            }
            // epilogue: + (Ui + cc) - WK, relu, tf32, -> Z
#pragma unroll
            for (int jt = 0; jt < 2; jt++) {
                int j = jb + jt*16 + g;
#pragma unroll
                for (int nt = 0; nt < 4; nt++) {
                    int ml = nb + nt*8 + 2*tk;
                    int mg = ch*64 + ml;
                    float2 wk0 = *(const float2*)(g_WK + (pb + j   )*AH + mg);
                    float2 wk1 = *(const float2*)(g_WK + (pb + j+8 )*AH + mg);
                    float u0 = sm[S_UIC + mg], u1 = sm[S_UIC + mg + 1];
                    *(float2*)&sm[S_Z + j*68 + ml] = make_float2(
                        tf32r(fmaxf(c1[jt][nt][0] + u0 - wk0.x, 0.f)),
                        tf32r(fmaxf(c1[jt][nt][1] + u1 - wk0.y, 0.f)));
                    *(float2*)&sm[S_Z + (j+8)*68 + ml] = make_float2(
                        tf32r(fmaxf(c1[jt][nt][2] + u0 - wk1.x, 0.f)),
                        tf32r(fmaxf(c1[jt][nt][3] + u1 - wk1.y, 0.f)));
                }
            }
            __syncthreads();
            // GEMM2 partial: C2[j, d] += Z @ W2[:, chunk]^T
#pragma unroll
            for (int s = 0; s < 8; s++) {
                int k0 = s*8;
                uint32_t a[2][4], b[4][2];
#pragma unroll
                for (int jt = 0; jt < 2; jt++) {
                    const float* p = sm + S_Z + (jb + jt*16)*68 + k0;
                    a[jt][0] = __float_as_uint(p[ g*68    + tk  ]);
                    a[jt][1] = __float_as_uint(p[(g+8)*68 + tk  ]);
                    a[jt][2] = __float_as_uint(p[ g*68    + tk+4]);
                    a[jt][3] = __float_as_uint(p[(g+8)*68 + tk+4]);
                }
#pragma unroll
                for (int nt = 0; nt < 4; nt++) {
                    const float* p = sm + S_W2 + (nb + nt*8 + g)*260 + ch*64 + k0;
                    b[nt][0] = __float_as_uint(p[tk]);
                    b[nt][1] = __float_as_uint(p[tk+4]);
                }
#pragma unroll
                for (int jt = 0; jt < 2; jt++)
#pragma unroll
                    for (int nt = 0; nt < 4; nt++) mma8(c2[jt][nt], a[jt], b[nt]);
            }
            __syncthreads();   // Z free for next chunk's epilogue
        }

        // ---- SIM -> Z region (am_b2 dropped: softmax-invariant) ----
#pragma unroll
        for (int jt = 0; jt < 2; jt++) {
            int j = jb + jt*16 + g;
#pragma unroll
            for (int nt = 0; nt < 4; nt++) {
                int dl = nb + nt*8 + 2*tk;
                *(float2*)&sm[S_Z + j*68 + dl] =
                    make_float2(c2[jt][nt][0], c2[jt][nt][1]);
                *(float2*)&sm[S_Z + (j+8)*68 + dl] =
                    make_float2(c2[jt][nt][2], c2[jt][nt][3]);
            }
        }

        // ---- VP: C3[j, d] = H1 @ PW2^T ----
        float c3[2][4][4] = {};
#pragma unroll
        for (int s = 0; s < 8; s++) {
            int k0 = s*8;
            uint32_t a[2][4], b[4][2];
#pragma unroll
            for (int jt = 0; jt < 2; jt++) {
                const float* p = sm + S_H1 + (jb + jt*16)*68 + k0;
                a[jt][0] = __float_as_uint(p[ g*68    + tk  ]);
                a[jt][1] = __float_as_uint(p[(g+8)*68 + tk  ]);
                a[jt][2] = __float_as_uint(p[ g*68    + tk+4]);
                a[jt][3] = __float_as_uint(p[(g+8)*68 + tk+4]);
            }
#pragma unroll
            for (int nt = 0; nt < 4; nt++) {
                const float* p = sm + S_PW2 + (nb + nt*8 + g)*68 + k0;
                b[nt][0] = __float_as_uint(p[tk]);
                b[nt][1] = __float_as_uint(p[tk+4]);
            }
#pragma unroll
            for (int jt = 0; jt < 2; jt++)
#pragma unroll
                for (int nt = 0; nt < 4; nt++) mma8(c3[jt][nt], a[jt], b[nt]);
        }
        __syncthreads();   // all VP reads of H1 done before overwrite

        // ---- VP epilogue: + pm_b2 + V -> H1 region ----
#pragma unroll
        for (int jt = 0; jt < 2; jt++) {
            int j = jb + jt*16 + g;
#pragma unroll
            for (int nt = 0; nt < 4; nt++) {
                int dl = nb + nt*8 + 2*tk;
                float2 v0 = *(const float2*)(g_V + (pb + j  )*DIM + dl);
                float2 v1 = *(const float2*)(g_V + (pb + j+8)*DIM + dl);
                float b0 = sm[S_PB2 + dl], b1 = sm[S_PB2 + dl + 1];
                *(float2*)&sm[S_H1 + j*68 + dl] = make_float2(
                    c3[jt][nt][0] + b0 + v0.x, c3[jt][nt][1] + b1 + v0.y);
                *(float2*)&sm[S_H1 + (j+8)*68 + dl] = make_float2(
                    c3[jt][nt][2] + b0 + v1.x, c3[jt][nt][3] + b1 + v1.y);
            }
        }
        __syncthreads();

        // ---- exact softmax over j + aggregate (SIM in Z, VP in H1) ----
        {
            int d = t & 63, g4 = t >> 6, jl = g4*32;
            float mx = -1e30f;
            for (int j = jl; j < jl+32; j++) mx = fmaxf(mx, sm[S_Z + j*68 + d]);
            sm[S_RED + g4*64 + d] = mx;
            __syncthreads();
            mx = fmaxf(fmaxf(sm[S_RED+d], sm[S_RED+64+d]),
                       fmaxf(sm[S_RED+128+d], sm[S_RED+192+d]));
            float se = 0.f, sa = 0.f;
            for (int j = jl; j < jl+32; j++) {
                float e = __expf(sm[S_Z + j*68 + d] - mx);
                se += e;
                sa  = fmaf(e, sm[S_H1 + j*68 + d], sa);
            }
            __syncthreads();
            sm[S_RED + g4*64 + d]       = se;
            sm[S_RED + 256 + g4*64 + d] = sa;
            __syncthreads();
            if (g4 == 0) {
                float S  = sm[S_RED+d] + sm[S_RED+64+d]
                         + sm[S_RED+128+d] + sm[S_RED+192+d];
                float Ag = sm[S_RED+256+d] + sm[S_RED+320+d]
                         + sm[S_RED+384+d] + sm[S_RED+448+d];
                out[(pb + i)*DIM + d] = Ag / S;
            }
        }
    }
}

// ---------------- launch ----------------
extern "C" void kernel_launch(void* const* d_in, const int* in_sizes, int n_in,
                              void* d_out, int out_size) {
    const float* x      = (const float*)d_in[0];
    const float* pos    = (const float*)d_in[1];
    const float* w_qkv  = (const float*)d_in[2];
    const float* pm_w1  = (const float*)d_in[3];
    const float* pm_b1  = (const float*)d_in[4];
    const float* pm_w2  = (const float*)d_in[5];
    const float* pm_b2  = (const float*)d_in[6];
    const float* am_w1  = (const float*)d_in[7];
    const float* am_b1  = (const float*)d_in[8];
    const float* am_w2  = (const float*)d_in[9];
    // am_b2 (d_in[10]) unused: constant over softmax axis
    float* out = (float*)d_out;

    cudaFuncSetAttribute(pt_mma,
                         cudaFuncAttributeMaxDynamicSharedMemorySize, SMEM_BYTES);

    prep_weights<<<70, 256>>>(pm_w2, am_w1, am_b1, pm_b2, am_w2);
    prep_points <<<BT*NPTS, 128>>>(x, pos, w_qkv, pm_w1, am_w1);
    pt_mma      <<<BT*32, 256, SMEM_BYTES>>>(pm_b1, pm_b2, out);
}

// round 10
// speedup vs baseline: 7.3613x; 2.2074x over previous
#include <cuda_runtime.h>
#include <cuda_fp16.h>
#include <cstdint>

#define BT   32
#define NPTS 128
#define DIM  64
#define AH   256
#define PH   64
#define PIN  34

// ---------------- mma helper: m16n8k16 fp16 -> fp32 ----------------
__device__ __forceinline__ void mma16(float c[4], const uint32_t a[4], const uint32_t b[2]) {
    asm volatile(
        "mma.sync.aligned.m16n8k16.row.col.f32.f16.f16.f32 "
        "{%0,%1,%2,%3},{%4,%5,%6,%7},{%8,%9},{%0,%1,%2,%3};"
        : "+f"(c[0]), "+f"(c[1]), "+f"(c[2]), "+f"(c[3])
        : "r"(a[0]), "r"(a[1]), "r"(a[2]), "r"(a[3]), "r"(b[0]), "r"(b[1]));
}
__device__ __forceinline__ uint32_t pkh2(float a, float b) {
    __half2 h = __floats2half2_rn(a, b);
    return *(uint32_t*)&h;
}

// ---------------- device scratch ----------------
__device__ float  g_A [BT*NPTS*DIM];   // p @ pm_w1.T           (fp32)
__device__ float  g_U [BT*NPTS*AH];    // q @ am_w1.T           (fp32)
__device__ float  g_WK[BT*NPTS*AH];    // k @ am_w1.T           (fp32)
__device__ float  g_V [BT*NPTS*DIM];   // v                     (fp32)
__device__ __half g_WCh [256*72];      // Wc[m][h]  stride 72
__device__ __half g_W2h [64*264];      // am_w2[d][m] stride 264
__device__ __half g_PW2h[64*72];       // pm_w2[d][h] stride 72
__device__ float  g_cc  [AH];          // am_b1 + pm_b2 @ am_w1.T

// ---------------- kernel 0: weight images (fp16) ----------------
__global__ void prep_weights(const float* __restrict__ pm_w2,
                             const float* __restrict__ am_w1,
                             const float* __restrict__ am_b1,
                             const float* __restrict__ pm_b2,
                             const float* __restrict__ am_w2) {
    int b = blockIdx.x, t = threadIdx.x;
    if (b < 64) {                       // Wc[m][h] = dot(am_w1[m,:], pm_w2[:,h])
        int gid = b * 256 + t;
        int m = gid >> 6, h = gid & 63;
        float s = 0.f;
#pragma unroll 8
        for (int d = 0; d < DIM; d++) s += am_w1[m*DIM + d] * pm_w2[d*PH + h];
        g_WCh[m*72 + h] = __float2half_rn(s);
        if (h < 8) g_WCh[m*72 + 64 + h] = __float2half_rn(0.f);
    } else if (b < 68) {                // W2 image [d][m] stride 264
        for (int i = (b-64)*4096 + t; i < (b-63)*4096; i += 256) {
            int d = i >> 8, m = i & 255;
            g_W2h[d*264 + m] = __float2half_rn(am_w2[i]);
            if (m < 8) g_W2h[d*264 + 256 + m] = __float2half_rn(0.f);
        }
    } else if (b == 68) {               // PW2 image [d][h] stride 72
        for (int i = t; i < 64*64; i += 256) {
            int d = i >> 6, h = i & 63;
            g_PW2h[d*72 + h] = __float2half_rn(pm_w2[i]);
            if (h < 8) g_PW2h[d*72 + 64 + h] = __float2half_rn(0.f);
        }
    } else {                            // cc
        int m = t;
        float s = am_b1[m];
#pragma unroll 8
        for (int d = 0; d < DIM; d++) s += pm_b2[d] * am_w1[m*DIM + d];
        g_cc[m] = s;
    }
}

// ---------------- kernel 1: per-point precompute (validated) ----------------
__global__ void prep_points(const float* __restrict__ x,
                            const float* __restrict__ pos,
                            const float* __restrict__ w_qkv,
                            const float* __restrict__ pm_w1,
                            const float* __restrict__ am_w1) {
    __shared__ float sx[DIM], sp[PIN], sq[DIM], sk[DIM];
    int pt = blockIdx.x;
    int bt = pt >> 7, n = pt & 127;
    int t  = threadIdx.x;

    if (t < DIM) sx[t] = x[(size_t)pt*DIM + t];
    if (t < PIN) {
        int c = t / 17, j = t % 17;
        sp[t] = pos[(((size_t)bt*17 + j)*3 + c)*NPTS + n];
    }
    __syncthreads();
    for (int m = t; m < 3*DIM; m += 128) {
        const float4* wr = (const float4*)(w_qkv + m*DIM);
        float s = 0.f;
#pragma unroll
        for (int i = 0; i < DIM/4; i++) {
            float4 w  = wr[i];
            float4 xv = ((const float4*)sx)[i];
            s += w.x*xv.x + w.y*xv.y + w.z*xv.z + w.w*xv.w;
        }
        if      (m <   DIM) sq[m]     = s;
        else if (m < 2*DIM) sk[m-DIM] = s;
        else g_V[(size_t)pt*DIM + (m-2*DIM)] = s;
    }
    if (t < DIM) {
        const float* wr = pm_w1 + t*PIN;
        float s = 0.f;
#pragma unroll
        for (int f = 0; f < PIN; f++) s += sp[f]*wr[f];
        g_A[(size_t)pt*DIM + t] = s;
    }
    __syncthreads();
    for (int m = t; m < AH; m += 128) {
        const float4* wr = (const float4*)(am_w1 + m*DIM);
        float su = 0.f, sw = 0.f;
#pragma unroll
        for (int i = 0; i < DIM/4; i++) {
            float4 w  = wr[i];
            float4 qv = ((const float4*)sq)[i];
            float4 kv = ((const float4*)sk)[i];
            su += w.x*qv.x + w.y*qv.y + w.z*qv.z + w.w*qv.w;
            sw += w.x*kv.x + w.y*kv.y + w.z*kv.z + w.w*kv.w;
        }
        g_U [(size_t)pt*AH + m] = su;
        g_WK[(size_t)pt*AH + m] = sw;
    }
}

// ---------------- kernel 2: fp16 warp-MMA, register softmax ----------------
// 512 threads = 16 warps, grid 4(j) x 4(n). Block = (bt, 4 i's).
// smem byte offsets
#define S_WC    0        // 256*72 half = 36864
#define S_W2    36864    // 64*264 half = 33792
#define S_PW2   70656    // 64*72  half = 9216
#define S_H1    79872    // 128*72 half = 18432
#define S_Z     98304    // 128*72 half = 18432
#define S_UIC   116736   // 256 f32
#define S_AI    117760   // 64 f32
#define S_PB1   118016   // 64 f32
#define S_PB2   118272   // 64 f32
#define S_RMX   118528   // 4*64 f32
#define S_RSUM  119552   // 4*64 f32
#define S_RAGG  120576   // 4*64 f32
#define SMEM_BYTES 121600

__global__ void __launch_bounds__(512, 1)
pt_f16(const float* __restrict__ pm_b1,
       const float* __restrict__ pm_b2,
       float* __restrict__ out) {
    extern __shared__ char smc[];
    __half* WCh  = (__half*)(smc + S_WC);
    __half* W2h  = (__half*)(smc + S_W2);
    __half* PW2h = (__half*)(smc + S_PW2);
    __half* H1h  = (__half*)(smc + S_H1);
    __half* Zh   = (__half*)(smc + S_Z);
    float* UIC = (float*)(smc + S_UIC);
    float* AI  = (float*)(smc + S_AI);
    float* PB1 = (float*)(smc + S_PB1);
    float* PB2 = (float*)(smc + S_PB2);
    float* RMX = (float*)(smc + S_RMX);
    float* RS  = (float*)(smc + S_RSUM);
    float* RA  = (float*)(smc + S_RAGG);

    int t = threadIdx.x, wid = t >> 5, lane = t & 31;
    int g = lane >> 2, tk = lane & 3;
    int wj = wid >> 2, wn = wid & 3;
    int jb = wj * 32, nb = wn * 16;
    int bt = blockIdx.x >> 5;
    int i0 = (blockIdx.x & 31) * 4;
    size_t pb = (size_t)bt * NPTS;

    // ---- weight images -> smem (uint4 copies) ----
    for (int idx = t; idx < 2304; idx += 512)
        ((uint4*)WCh)[idx] = ((const uint4*)g_WCh)[idx];
    for (int idx = t; idx < 2112; idx += 512)
        ((uint4*)W2h)[idx] = ((const uint4*)g_W2h)[idx];
    for (int idx = t; idx < 576; idx += 512)
        ((uint4*)PW2h)[idx] = ((const uint4*)g_PW2h)[idx];
    if (t < 64) { PB1[t] = pm_b1[t]; PB2[t] = pm_b2[t]; }

    for (int ii = 0; ii < 4; ii++) {
        int i = i0 + ii;
        __syncthreads();                       // prev i consumers done / weights in
        if      (t < 256) UIC[t]     = g_U[(pb + i)*AH + t] + g_cc[t];
        else if (t < 320) AI[t-256]  = g_A[(pb + i)*DIM + (t-256)];
        __syncthreads();

        // ---- H1[j][h] = fp16(relu(a_i - a_j + pm_b1)), stride 72 halfs ----
        {
            int j  = t >> 2;
            int hb = (t & 3) * 16;
            const float4* ap = (const float4*)(g_A + (pb + j)*DIM + hb);
            float4 A0 = ap[0], A1 = ap[1], A2 = ap[2], A3 = ap[3];
            float av[16] = {A0.x,A0.y,A0.z,A0.w, A1.x,A1.y,A1.z,A1.w,
                            A2.x,A2.y,A2.z,A2.w, A3.x,A3.y,A3.z,A3.w};
#pragma unroll
            for (int q = 0; q < 8; q++) {
                int h = hb + 2*q;
                float v0 = fmaxf(AI[h]   - av[2*q]   + PB1[h],   0.f);
                float v1 = fmaxf(AI[h+1] - av[2*q+1] + PB1[h+1], 0.f);
                *(uint32_t*)&H1h[j*72 + h] = pkh2(v0, v1);
            }
        }
        __syncthreads();

        // ---- hoisted A-fragments of H1 (used by GEMM1 all chunks + VP) ----
        uint32_t afr[4][2][4];
#pragma unroll
        for (int s = 0; s < 4; s++)
#pragma unroll
            for (int jt = 0; jt < 2; jt++) {
                const __half* p = &H1h[(jb + jt*16 + g)*72 + s*16 + 2*tk];
                afr[s][jt][0] = *(const uint32_t*)p;
                afr[s][jt][1] = *(const uint32_t*)(p + 8*72);
                afr[s][jt][2] = *(const uint32_t*)(p + 8);
                afr[s][jt][3] = *(const uint32_t*)(p + 8*72 + 8);
            }

        float c2[2][2][4] = {};                 // SIM accumulators (j,d)
        for (int ch = 0; ch < 4; ch++) {
            // ---- GEMM1 chunk: C1 = H1 @ Wc[ch]^T ----
            float c1[2][2][4] = {};
#pragma unroll
            for (int s = 0; s < 4; s++) {
                uint32_t b[2][2];
#pragma unroll
                for (int nt = 0; nt < 2; nt++) {
                    const __half* p = &WCh[(ch*64 + nb + nt*8 + g)*72 + s*16 + 2*tk];
                    b[nt][0] = *(const uint32_t*)p;
                    b[nt][1] = *(const uint32_t*)(p + 8);
                }
#pragma unroll
                for (int jt = 0; jt < 2; jt++)
#pragma unroll
                    for (int nt = 0; nt < 2; nt++) mma16(c1[jt][nt], afr[s][jt], b[nt]);
            }
            // ---- epilogue: + (Ui+cc) - WK, relu, fp16 -> Z ----
#pragma unroll
            for (int jt = 0; jt < 2; jt++) {
                int j = jb + jt*16 + g;
#pragma unroll
                for (int nt = 0; nt < 2; nt++) {
                    int ml = nb + nt*8 + 2*tk;
                    int m  = ch*64 + ml;
                    float u0 = UIC[m], u1 = UIC[m+1];
                    float2 wk0 = *(const float2*)(g_WK + (pb + j  )*AH + m);
                    float2 wk1 = *(const float2*)(g_WK + (pb + j+8)*AH + m);
                    *(uint32_t*)&Zh[j*72 + ml] = pkh2(
                        fmaxf(c1[jt][nt][0] + u0 - wk0.x, 0.f),
                        fmaxf(c1[jt][nt][1] + u1 - wk0.y, 0.f));
                    *(uint32_t*)&Zh[(j+8)*72 + ml] = pkh2(
                        fmaxf(c1[jt][nt][2] + u0 - wk1.x, 0.f),
                        fmaxf(c1[jt][nt][3] + u1 - wk1.y, 0.f));
                }
            }
            __syncthreads();
            // ---- GEMM2 partial: C2 += Z @ W2[:,ch]^T ----
#pragma unroll
            for (int s = 0; s < 4; s++) {
                uint32_t za[2][4], b2[2][2];
#pragma unroll
                for (int jt = 0; jt < 2; jt++) {
                    const __half* p = &Zh[(jb + jt*16 + g)*72 + s*16 + 2*tk];
                    za[jt][0] = *(const uint32_t*)p;
                    za[jt][1] = *(const uint32_t*)(p + 8*72);
                    za[jt][2] = *(const uint32_t*)(p + 8);
                    za[jt][3] = *(const uint32_t*)(p + 8*72 + 8);
                }
#pragma unroll
                for (int nt = 0; nt < 2; nt++) {
                    const __half* p = &W2h[(nb + nt*8 + g)*264 + ch*64 + s*16 + 2*tk];
                    b2[nt][0] = *(const uint32_t*)p;
                    b2[nt][1] = *(const uint32_t*)(p + 8);
                }
#pragma unroll
                for (int jt = 0; jt < 2; jt++)
#pragma unroll
                    for (int nt = 0; nt < 2; nt++) mma16(c2[jt][nt], za[jt], b2[nt]);
            }
            __syncthreads();   // Z free for next chunk
        }

        // ---- VP: C3 = H1 @ pm_w2^T ----
        float c3[2][2][4] = {};
#pragma unroll
        for (int s = 0; s < 4; s++) {
            uint32_t b[2][2];
#pragma unroll
            for (int nt = 0; nt < 2; nt++) {
                const __half* p = &PW2h[(nb + nt*8 + g)*72 + s*16 + 2*tk];
                b[nt][0] = *(const uint32_t*)p;
                b[nt][1] = *(const uint32_t*)(p + 8);
            }
#pragma unroll
            for (int jt = 0; jt < 2; jt++)
#pragma unroll
                for (int nt = 0; nt < 2; nt++) mma16(c3[jt][nt], afr[s][jt], b[nt]);
        }

        // ---- softmax in registers (am_b2 dropped: softmax-invariant) ----
        // pass A: warp-local max over this warp's 32 j, per d
        float lm[2][2];
#pragma unroll
        for (int nt = 0; nt < 2; nt++)
#pragma unroll
            for (int cp = 0; cp < 2; cp++)
                lm[nt][cp] = fmaxf(fmaxf(c2[0][nt][cp], c2[0][nt][cp+2]),
                                   fmaxf(c2[1][nt][cp], c2[1][nt][cp+2]));
#pragma unroll
        for (int mk = 4; mk <= 16; mk <<= 1)
#pragma unroll
            for (int nt = 0; nt < 2; nt++)
#pragma unroll
                for (int cp = 0; cp < 2; cp++)
                    lm[nt][cp] = fmaxf(lm[nt][cp],
                        __shfl_xor_sync(0xffffffffu, lm[nt][cp], mk));
        if (lane < 4)
#pragma unroll
            for (int nt = 0; nt < 2; nt++)
#pragma unroll
                for (int cp = 0; cp < 2; cp++)
                    RMX[wj*64 + nb + nt*8 + 2*tk + cp] = lm[nt][cp];
        __syncthreads();

        // pass B: exp-sum + weighted vp sum
        float ls[2][2] = {}, la[2][2] = {};
#pragma unroll
        for (int nt = 0; nt < 2; nt++)
#pragma unroll
            for (int cp = 0; cp < 2; cp++) {
                int d = nb + nt*8 + 2*tk + cp;
                float M = fmaxf(fmaxf(RMX[d], RMX[64+d]),
                                fmaxf(RMX[128+d], RMX[192+d]));
                float bp2 = PB2[d];
#pragma unroll
                for (int jt = 0; jt < 2; jt++)
#pragma unroll
                    for (int rs = 0; rs < 2; rs++) {
                        int j = jb + jt*16 + g + rs*8;
                        float e  = __expf(c2[jt][nt][cp + 2*rs] - M);
                        float vp = c3[jt][nt][cp + 2*rs] + bp2
                                 + g_V[(pb + j)*DIM + d];
                        ls[nt][cp] += e;
                        la[nt][cp] = fmaf(e, vp, la[nt][cp]);
                    }
            }
#pragma unroll
        for (int mk = 4; mk <= 16; mk <<= 1)
#pragma unroll
            for (int nt = 0; nt < 2; nt++)
#pragma unroll
                for (int cp = 0; cp < 2; cp++) {
                    ls[nt][cp] += __shfl_xor_sync(0xffffffffu, ls[nt][cp], mk);
                    la[nt][cp] += __shfl_xor_sync(0xffffffffu, la[nt][cp], mk);
                }
        if (lane < 4)
#pragma unroll
            for (int nt = 0; nt < 2; nt++)
#pragma unroll
                for (int cp = 0; cp < 2; cp++) {
                    int d = nb + nt*8 + 2*tk + cp;
                    RS[wj*64 + d] = ls[nt][cp];
                    RA[wj*64 + d] = la[nt][cp];
                }
        __syncthreads();

        // pass C
        if (t < 64) {
            float S  = RS[t] + RS[64+t] + RS[128+t] + RS[192+t];
            float Ag = RA[t] + RA[64+t] + RA[128+t] + RA[192+t];
            out[(pb + i)*DIM + t] = Ag / S;
        }
    }
}

// ---------------- launch ----------------
extern "C" void kernel_launch(void* const* d_in, const int* in_sizes, int n_in,
                              void* d_out, int out_size) {
    const float* x      = (const float*)d_in[0];
    const float* pos    = (const float*)d_in[1];
    const float* w_qkv  = (const float*)d_in[2];
    const float* pm_w1  = (const float*)d_in[3];
    const float* pm_b1  = (const float*)d_in[4];
    const float* pm_w2  = (const float*)d_in[5];
    const float* pm_b2  = (const float*)d_in[6];
    const float* am_w1  = (const float*)d_in[7];
    const float* am_b1  = (const float*)d_in[8];
    const float* am_w2  = (const float*)d_in[9];
    // am_b2 (d_in[10]) unused: constant over softmax axis
    float* out = (float*)d_out;

    cudaFuncSetAttribute(pt_f16,
                         cudaFuncAttributeMaxDynamicSharedMemorySize, SMEM_BYTES);

    prep_weights<<<70, 256>>>(pm_w2, am_w1, am_b1, pm_b2, am_w2);
    prep_points <<<BT*NPTS, 128>>>(x, pos, w_qkv, pm_w1, am_w1);
    pt_f16      <<<BT*32, 512, SMEM_BYTES>>>(pm_b1, pm_b2, out);
}